// round 1
// baseline (speedup 1.0000x reference)
#include <cuda_runtime.h>

// ---------------------------------------------------------------------------
// GPT-2 attention block, fp32 baseline.
//   qkv = x @ w_attn + b_attn          [8192, 3072]
//   att = causal_softmax(q k^T / 8) v  [8192, 1024]  (flash, per (b,h,qtile))
//   out = att @ w_proj + b_proj        [8192, 1024]
// ---------------------------------------------------------------------------

#define BATCH  4
#define SEQ    2048
#define DMODEL 1024
#define NHEAD  16
#define HDIM   64
#define MTOT   (BATCH * SEQ)
#define QKV_LD (3 * DMODEL)

// Scratch (allocation-free rule: __device__ globals)
__device__ float g_qkv[(size_t)MTOT * QKV_LD];   // 96 MB
__device__ float g_att[(size_t)MTOT * DMODEL];   // 32 MB

// ---------------------------------------------------------------------------
// SGEMM + bias: C[M,N] = A[M,K] @ B[K,N] + bias[N]
// 128x128 block tile, BK=8, 256 threads, 8x8 per thread.
// ---------------------------------------------------------------------------
#define GBM 128
#define GBN 128
#define GBK 8

__device__ __forceinline__ void sgemm_body(
    const float* __restrict__ A, const float* __restrict__ B,
    const float* __restrict__ bias, float* __restrict__ C,
    int M, int N, int K)
{
    __shared__ float As[GBK][GBM + 4];   // k-major (A transposed in smem)
    __shared__ float Bs[GBK][GBN];

    const int tid = threadIdx.x;
    const int tx  = tid & 15;
    const int ty  = tid >> 4;
    const int m0  = blockIdx.y * GBM;
    const int n0  = blockIdx.x * GBN;

    const int arow = tid >> 1;          // 0..127
    const int acol = (tid & 1) << 2;    // 0 or 4 (k within tile)
    const int brow = tid >> 5;          // 0..7
    const int bcol = (tid & 31) << 2;   // 0..124

    const float* Ap = A + (m0 + arow) * K + acol;
    const float* Bp = B + brow * N + n0 + bcol;

    float acc[8][8];
    #pragma unroll
    for (int i = 0; i < 8; i++)
        #pragma unroll
        for (int j = 0; j < 8; j++) acc[i][j] = 0.0f;

    for (int k0 = 0; k0 < K; k0 += GBK) {
        float4 av = *(const float4*)(Ap + k0);
        float4 bv = *(const float4*)(Bp + k0 * N);
        __syncthreads();
        As[acol + 0][arow] = av.x;
        As[acol + 1][arow] = av.y;
        As[acol + 2][arow] = av.z;
        As[acol + 3][arow] = av.w;
        *(float4*)&Bs[brow][bcol] = bv;
        __syncthreads();

        #pragma unroll
        for (int kk = 0; kk < GBK; kk++) {
            float a[8], b[8];
            *(float4*)&a[0] = *(const float4*)&As[kk][ty * 8];
            *(float4*)&a[4] = *(const float4*)&As[kk][ty * 8 + 4];
            *(float4*)&b[0] = *(const float4*)&Bs[kk][tx * 8];
            *(float4*)&b[4] = *(const float4*)&Bs[kk][tx * 8 + 4];
            #pragma unroll
            for (int i = 0; i < 8; i++)
                #pragma unroll
                for (int j = 0; j < 8; j++)
                    acc[i][j] = fmaf(a[i], b[j], acc[i][j]);
        }
    }

    float bz[8];
    #pragma unroll
    for (int j = 0; j < 8; j++) bz[j] = bias[n0 + tx * 8 + j];

    #pragma unroll
    for (int i = 0; i < 8; i++) {
        int row = m0 + ty * 8 + i;
        float4 c0 = make_float4(acc[i][0] + bz[0], acc[i][1] + bz[1],
                                acc[i][2] + bz[2], acc[i][3] + bz[3]);
        float4 c1 = make_float4(acc[i][4] + bz[4], acc[i][5] + bz[5],
                                acc[i][6] + bz[6], acc[i][7] + bz[7]);
        *(float4*)&C[row * N + n0 + tx * 8]     = c0;
        *(float4*)&C[row * N + n0 + tx * 8 + 4] = c1;
    }
}

__global__ __launch_bounds__(256)
void sgemm_qkv(const float* __restrict__ x, const float* __restrict__ w,
               const float* __restrict__ bias)
{
    sgemm_body(x, w, bias, g_qkv, MTOT, 3 * DMODEL, DMODEL);
}

__global__ __launch_bounds__(256)
void sgemm_proj(const float* __restrict__ w, const float* __restrict__ bias,
                float* __restrict__ out)
{
    sgemm_body(g_att, w, bias, out, MTOT, DMODEL, DMODEL);
}

// ---------------------------------------------------------------------------
// Causal flash attention.
// Block = (b, h, 64-row q-tile), 256 threads (16x16 grid, 4x4 microtiles).
// Qs/Ks stored d-major (transposed) so both GEMMs read float4 fragments.
// Ps stored k-major. Vs stored [k][d].
// ---------------------------------------------------------------------------
#define AST 68                                  // padded stride (floats)
#define ATT_SMEM (4 * 64 * AST * sizeof(float)) // 69632 bytes

__global__ __launch_bounds__(256)
void attn_kernel()
{
    extern __shared__ float sm[];
    float* Qs = sm;                 // [d][r]
    float* Ks = sm + 64 * AST;      // [d][c]
    float* Ps = sm + 2 * 64 * AST;  // [k][r]
    float* Vs = sm + 3 * 64 * AST;  // [k][d]

    const int tid = threadIdx.x;
    const int tx  = tid & 15;
    const int ty  = tid >> 4;
    const int tx4 = tx * 4;
    const int ty4 = ty * 4;
    const int qtile = blockIdx.x;
    const int bh    = blockIdx.y;
    const int b = bh >> 4;
    const int h = bh & 15;
    const int q0 = qtile * 64;

    const float* qbase = g_qkv + (size_t)(b * SEQ + q0) * QKV_LD + h * HDIM;
    const float* kbase = g_qkv + (size_t)(b * SEQ) * QKV_LD + DMODEL + h * HDIM;
    const float* vbase = kbase + DMODEL;

    // Load Q tile transposed: Qs[d][r]
    #pragma unroll
    for (int it = 0; it < 4; it++) {
        int idx = tid + it * 256;          // 0..1023
        int r   = idx >> 4;                // 0..63
        int dv  = (idx & 15) << 2;         // 0..60
        float4 v = *(const float4*)(qbase + (size_t)r * QKV_LD + dv);
        Qs[(dv + 0) * AST + r] = v.x;
        Qs[(dv + 1) * AST + r] = v.y;
        Qs[(dv + 2) * AST + r] = v.z;
        Qs[(dv + 3) * AST + r] = v.w;
    }

    float o[4][4];
    #pragma unroll
    for (int i = 0; i < 4; i++)
        #pragma unroll
        for (int j = 0; j < 4; j++) o[i][j] = 0.0f;
    float mrun[4] = {-1e30f, -1e30f, -1e30f, -1e30f};
    float lrun[4] = {0.0f, 0.0f, 0.0f, 0.0f};

    for (int jt = 0; jt <= qtile; jt++) {
        __syncthreads();   // previous PV reads of Ks/Vs/Ps done

        // Load K (transposed) and V tiles
        #pragma unroll
        for (int it = 0; it < 4; it++) {
            int idx = tid + it * 256;
            int r   = idx >> 4;
            int dv  = (idx & 15) << 2;
            size_t goff = (size_t)(jt * 64 + r) * QKV_LD + dv;
            float4 kv = *(const float4*)(kbase + goff);
            Ks[(dv + 0) * AST + r] = kv.x;
            Ks[(dv + 1) * AST + r] = kv.y;
            Ks[(dv + 2) * AST + r] = kv.z;
            Ks[(dv + 3) * AST + r] = kv.w;
            float4 vv = *(const float4*)(vbase + goff);
            *(float4*)&Vs[r * AST + dv] = vv;
        }
        __syncthreads();

        // S = Q @ K^T
        float s[4][4];
        #pragma unroll
        for (int i = 0; i < 4; i++)
            #pragma unroll
            for (int j = 0; j < 4; j++) s[i][j] = 0.0f;

        #pragma unroll 8
        for (int d = 0; d < 64; d++) {
            float4 a  = *(const float4*)&Qs[d * AST + ty4];
            float4 bq = *(const float4*)&Ks[d * AST + tx4];
            const float af[4] = {a.x, a.y, a.z, a.w};
            const float bf[4] = {bq.x, bq.y, bq.z, bq.w};
            #pragma unroll
            for (int i = 0; i < 4; i++)
                #pragma unroll
                for (int j = 0; j < 4; j++)
                    s[i][j] = fmaf(af[i], bf[j], s[i][j]);
        }

        // Scale + causal mask (matches reference: masked entries = exactly -1e9)
        if (jt == qtile) {
            #pragma unroll
            for (int i = 0; i < 4; i++)
                #pragma unroll
                for (int j = 0; j < 4; j++)
                    s[i][j] = (tx4 + j > ty4 + i) ? -1e9f : s[i][j] * 0.125f;
        } else {
            #pragma unroll
            for (int i = 0; i < 4; i++)
                #pragma unroll
                for (int j = 0; j < 4; j++)
                    s[i][j] *= 0.125f;
        }

        // Row max across the 16 tx lanes (xor<16 stays in-group)
        float mt[4];
        #pragma unroll
        for (int i = 0; i < 4; i++)
            mt[i] = fmaxf(fmaxf(s[i][0], s[i][1]), fmaxf(s[i][2], s[i][3]));
        #pragma unroll
        for (int off = 8; off >= 1; off >>= 1)
            #pragma unroll
            for (int i = 0; i < 4; i++)
                mt[i] = fmaxf(mt[i], __shfl_xor_sync(0xffffffffu, mt[i], off));

        float fac[4];
        #pragma unroll
        for (int i = 0; i < 4; i++) {
            float mn = fmaxf(mrun[i], mt[i]);
            fac[i] = __expf(mrun[i] - mn);
            mrun[i] = mn;
        }

        float lt[4];
        #pragma unroll
        for (int i = 0; i < 4; i++) {
            lt[i] = 0.0f;
            #pragma unroll
            for (int j = 0; j < 4; j++) {
                s[i][j] = __expf(s[i][j] - mrun[i]);
                lt[i] += s[i][j];
            }
        }
        #pragma unroll
        for (int off = 8; off >= 1; off >>= 1)
            #pragma unroll
            for (int i = 0; i < 4; i++)
                lt[i] += __shfl_xor_sync(0xffffffffu, lt[i], off);

        #pragma unroll
        for (int i = 0; i < 4; i++) {
            lrun[i] = lrun[i] * fac[i] + lt[i];
            #pragma unroll
            for (int j = 0; j < 4; j++) o[i][j] *= fac[i];
        }

        // Write P transposed: Ps[k][r]
        #pragma unroll
        for (int i = 0; i < 4; i++)
            #pragma unroll
            for (int j = 0; j < 4; j++)
                Ps[(tx4 + j) * AST + ty4 + i] = s[i][j];
        __syncthreads();

        // O += P @ V
        #pragma unroll 8
        for (int k = 0; k < 64; k++) {
            float4 a = *(const float4*)&Ps[k * AST + ty4];
            float4 v = *(const float4*)&Vs[k * AST + tx4];
            const float af[4] = {a.x, a.y, a.z, a.w};
            const float vf[4] = {v.x, v.y, v.z, v.w};
            #pragma unroll
            for (int i = 0; i < 4; i++)
                #pragma unroll
                for (int j = 0; j < 4; j++)
                    o[i][j] = fmaf(af[i], vf[j], o[i][j]);
        }
    }

    // Normalize + write merged-head layout [B, S, D]
    #pragma unroll
    for (int i = 0; i < 4; i++) {
        float inv = 1.0f / lrun[i];
        size_t row = (size_t)(b * SEQ + q0 + ty4 + i);
        float4 c = make_float4(o[i][0] * inv, o[i][1] * inv,
                               o[i][2] * inv, o[i][3] * inv);
        *(float4*)&g_att[row * DMODEL + h * HDIM + tx4] = c;
    }
}

// ---------------------------------------------------------------------------
extern "C" void kernel_launch(void* const* d_in, const int* in_sizes, int n_in,
                              void* d_out, int out_size)
{
    const float* x      = (const float*)d_in[0];
    const float* w_attn = (const float*)d_in[1];
    const float* b_attn = (const float*)d_in[2];
    const float* w_proj = (const float*)d_in[3];
    const float* b_proj = (const float*)d_in[4];
    float* out = (float*)d_out;

    // Non-stream API: capture-safe, idempotent, called every launch.
    cudaFuncSetAttribute(attn_kernel,
                         cudaFuncAttributeMaxDynamicSharedMemorySize,
                         (int)ATT_SMEM);

    dim3 blk(256);
    sgemm_qkv<<<dim3(3 * DMODEL / GBN, MTOT / GBM), blk>>>(x, w_attn, b_attn);
    attn_kernel<<<dim3(SEQ / 64, BATCH * NHEAD), blk, ATT_SMEM>>>();
    sgemm_proj<<<dim3(DMODEL / GBN, MTOT / GBM), blk>>>(w_proj, b_proj, out);
}

// round 3
// speedup vs baseline: 1.4665x; 1.4665x over previous
#include <cuda_runtime.h>
#include <cuda_bf16.h>
#include <cstdint>

// ---------------------------------------------------------------------------
// GPT-2 attention block.
//   qkv = x @ w_attn + b_attn      -> mma.sync bf16 hi/lo split GEMM
//   att = flash attention (fp32 SIMT)
//   out = att @ w_proj + b_proj    -> mma.sync bf16 hi/lo split GEMM
// (tcgen05 is unavailable: harness PTX target is family-common sm_103.)
// ---------------------------------------------------------------------------

#define BATCH  4
#define SEQ    2048
#define DMODEL 1024
#define NHEAD  16
#define HDIM   64
#define MTOT   (BATCH * SEQ)
#define QKV_LD (3 * DMODEL)
#define GK     1024

// Scratch (allocation-free rule: __device__ globals)
__device__ float g_qkv[(size_t)MTOT * QKV_LD];   // 96 MB
__device__ float g_att[(size_t)MTOT * DMODEL];   // 32 MB
__device__ __nv_bfloat16 g_wa_hi[3 * DMODEL * DMODEL];  // w_attn^T hi [3072][1024]
__device__ __nv_bfloat16 g_wa_lo[3 * DMODEL * DMODEL];
__device__ __nv_bfloat16 g_wp_hi[DMODEL * DMODEL];      // w_proj^T hi [1024][1024]
__device__ __nv_bfloat16 g_wp_lo[DMODEL * DMODEL];

// ---------------------------------------------------------------------------
__device__ __forceinline__ uint32_t smem_to_u32(const void* p) {
    uint32_t a;
    asm("{ .reg .u64 t; cvta.to.shared.u64 t, %1; cvt.u32.u64 %0, t; }"
        : "=r"(a) : "l"(p));
    return a;
}

__device__ __forceinline__ void ldsm_x4(uint32_t& r0, uint32_t& r1,
                                        uint32_t& r2, uint32_t& r3, uint32_t a) {
    asm volatile("ldmatrix.sync.aligned.m8n8.x4.shared.b16 {%0,%1,%2,%3}, [%4];"
                 : "=r"(r0), "=r"(r1), "=r"(r2), "=r"(r3) : "r"(a));
}

__device__ __forceinline__ void mma16816(float* d, const uint32_t* a,
                                         uint32_t b0, uint32_t b1) {
    asm volatile(
        "mma.sync.aligned.m16n8k16.row.col.f32.bf16.bf16.f32 "
        "{%0,%1,%2,%3}, {%4,%5,%6,%7}, {%8,%9}, {%0,%1,%2,%3};"
        : "+f"(d[0]), "+f"(d[1]), "+f"(d[2]), "+f"(d[3])
        : "r"(a[0]), "r"(a[1]), "r"(a[2]), "r"(a[3]), "r"(b0), "r"(b1));
}

#define CP_ASYNC8(dst, src) \
    asm volatile("cp.async.ca.shared.global [%0], [%1], 8;" :: "r"(dst), "l"(src) : "memory")
#define CP_COMMIT() asm volatile("cp.async.commit_group;" ::: "memory")
#define CP_WAIT0()  asm volatile("cp.async.wait_group 0;" ::: "memory")

// ---------------------------------------------------------------------------
// Weight transpose + bf16 hi/lo split:  w[K][N] fp32 -> out[N][K] bf16 x2
// ---------------------------------------------------------------------------
__device__ __forceinline__ void transpose_split_body(
    const float* __restrict__ w, __nv_bfloat16* __restrict__ hi,
    __nv_bfloat16* __restrict__ lo, int K, int N)
{
    __shared__ float t[32][33];
    const int n0 = blockIdx.x * 32, k0 = blockIdx.y * 32;
    const int tx = threadIdx.x, ty = threadIdx.y;
    #pragma unroll
    for (int i = ty; i < 32; i += 8)
        t[i][tx] = w[(size_t)(k0 + i) * N + n0 + tx];
    __syncthreads();
    #pragma unroll
    for (int i = ty; i < 32; i += 8) {
        float v = t[tx][i];                       // = w[k0+tx][n0+i]
        __nv_bfloat16 h = __float2bfloat16(v);
        size_t idx = (size_t)(n0 + i) * K + k0 + tx;
        hi[idx] = h;
        lo[idx] = __float2bfloat16(v - __bfloat162float(h));
    }
}
__global__ void trans_wa(const float* __restrict__ w) {
    transpose_split_body(w, g_wa_hi, g_wa_lo, DMODEL, 3 * DMODEL);
}
__global__ void trans_wp(const float* __restrict__ w) {
    transpose_split_body(w, g_wp_hi, g_wp_lo, DMODEL, DMODEL);
}

// ---------------------------------------------------------------------------
// mma.sync GEMM: C[M,N] = A[M,1024]fp32 * BT[N,1024](bf16 hi/lo) + bias
// CTA 128x128, K-step 32, 8 warps (4x2), warp tile 32x64.
// Smem tiles 80B row stride (conflict-free ldmatrix), double buffered.
// ---------------------------------------------------------------------------
#define TK      32
#define NSTEP   (GK / TK)          // 32
#define ROWB    80                 // bytes per smem row (32 bf16 + pad)
#define TILEB   (128 * ROWB)       // 10240 bytes per tile-half
// dynamic smem: A[s][h] then B[s][h]
#define SM_A(s, h) (((s) * 2 + (h)) * TILEB)
#define SM_B(s, h) (40960 + ((s) * 2 + (h)) * TILEB)
#define GSMEM   81920

__device__ __forceinline__ void gemm_mma_body(
    const float* __restrict__ A, const __nv_bfloat16* __restrict__ BTh,
    const __nv_bfloat16* __restrict__ BTl, const float* __restrict__ bias,
    float* __restrict__ C, int N)
{
    extern __shared__ char smem[];
    const uint32_t sb = smem_to_u32(smem);
    const int tid  = threadIdx.x;
    const int wid  = tid >> 5;
    const int lane = tid & 31;
    const int wm   = wid & 3;          // 0..3 -> m offset 32*wm
    const int wn   = wid >> 2;         // 0..1 -> n offset 64*wn
    const int gid  = lane >> 2;
    const int tig  = lane & 3;
    const int m0   = blockIdx.y * 128;
    const int n0   = blockIdx.x * 128;

    float d[2][8][4];
    #pragma unroll
    for (int mt = 0; mt < 2; mt++)
        #pragma unroll
        for (int nt = 0; nt < 8; nt++)
            #pragma unroll
            for (int c = 0; c < 4; c++) d[mt][nt][c] = 0.0f;

    // A-load indices: 4 float4 per thread per step
    const int arow = tid >> 1;               // 0..127
    const int ac8  = (tid & 1) << 2;         // 0 or 4 -> float4 index base
    // reinterpreted: idx scheme below

    // ldmatrix lane addresses (byte offsets within a tile-half)
    const uint32_t a_off = (uint32_t)((wm * 32 + (lane & 7) + ((lane >> 3) & 1) * 8) * ROWB
                                      + (lane >> 4) * 16);
    const uint32_t b_off = (uint32_t)((wn * 64 + ((lane >> 4) & 1) * 8 + (lane & 7)) * ROWB
                                      + ((lane >> 3) & 1) * 16);

    float4 areg[4];

    auto ldg_A = [&](int t) {
        const int k0 = t * TK;
        #pragma unroll
        for (int i = 0; i < 4; i++) {
            int idx = tid + i * 256;          // 0..1023
            int row = idx >> 3;               // 0..127
            int c4  = idx & 7;                // float4 index within 32 cols
            areg[i] = *(const float4*)(A + (size_t)(m0 + row) * GK + k0 + c4 * 4);
        }
    };
    auto cpasync_B = [&](int t, int s) {
        const int k0 = t * TK;
        #pragma unroll
        for (int i = 0; i < 8; i++) {
            int idx  = tid + i * 256;         // 0..2047
            int half = idx >> 10;
            int row  = (idx >> 3) & 127;
            int c    = idx & 7;               // 4-elem (8B) chunk
            uint32_t dst = sb + SM_B(s, half) + row * ROWB + c * 8;
            const __nv_bfloat16* src =
                (half ? BTl : BTh) + (size_t)(n0 + row) * GK + k0 + c * 4;
            CP_ASYNC8(dst, src);
        }
        CP_COMMIT();
    };
    auto sts_A = [&](int s) {
        #pragma unroll
        for (int i = 0; i < 4; i++) {
            int idx = tid + i * 256;
            int row = idx >> 3;
            int c4  = idx & 7;
            float4 v = areg[i];
            float hx = __bfloat162float(__float2bfloat16(v.x));
            float hy = __bfloat162float(__float2bfloat16(v.y));
            float hz = __bfloat162float(__float2bfloat16(v.z));
            float hw = __bfloat162float(__float2bfloat16(v.w));
            __nv_bfloat162 h0 = __floats2bfloat162_rn(hx, hy);
            __nv_bfloat162 h1 = __floats2bfloat162_rn(hz, hw);
            __nv_bfloat162 l0 = __floats2bfloat162_rn(v.x - hx, v.y - hy);
            __nv_bfloat162 l1 = __floats2bfloat162_rn(v.z - hz, v.w - hw);
            uint32_t off = (uint32_t)(row * ROWB + c4 * 8);
            *(__nv_bfloat162*)(smem + SM_A(s, 0) + off)     = h0;
            *(__nv_bfloat162*)(smem + SM_A(s, 0) + off + 4) = h1;
            *(__nv_bfloat162*)(smem + SM_A(s, 1) + off)     = l0;
            *(__nv_bfloat162*)(smem + SM_A(s, 1) + off + 4) = l1;
        }
    };

    // prologue: fill buffer 0
    ldg_A(0);
    cpasync_B(0, 0);
    sts_A(0);
    CP_WAIT0();
    __syncthreads();

    #pragma unroll 1
    for (int t = 0; t < NSTEP; t++) {
        const int b  = t & 1;
        const int nb = b ^ 1;
        if (t + 1 < NSTEP) {
            ldg_A(t + 1);
            cpasync_B(t + 1, nb);
        }

        const uint32_t ah_base = sb + SM_A(b, 0) + a_off;
        const uint32_t al_base = sb + SM_A(b, 1) + a_off;
        const uint32_t bh_base = sb + SM_B(b, 0) + b_off;
        const uint32_t bl_base = sb + SM_B(b, 1) + b_off;

        #pragma unroll
        for (int kk = 0; kk < 2; kk++) {
            const uint32_t ko = kk * 32;
            uint32_t Ah[2][4], Al[2][4];
            ldsm_x4(Ah[0][0], Ah[0][1], Ah[0][2], Ah[0][3], ah_base + ko);
            ldsm_x4(Ah[1][0], Ah[1][1], Ah[1][2], Ah[1][3], ah_base + 16 * ROWB + ko);
            ldsm_x4(Al[0][0], Al[0][1], Al[0][2], Al[0][3], al_base + ko);
            ldsm_x4(Al[1][0], Al[1][1], Al[1][2], Al[1][3], al_base + 16 * ROWB + ko);

            uint32_t Bh[8][2], Bl[8][2];
            #pragma unroll
            for (int p = 0; p < 4; p++) {
                ldsm_x4(Bh[2 * p][0], Bh[2 * p][1], Bh[2 * p + 1][0], Bh[2 * p + 1][1],
                        bh_base + p * 16 * ROWB + ko);
                ldsm_x4(Bl[2 * p][0], Bl[2 * p][1], Bl[2 * p + 1][0], Bl[2 * p + 1][1],
                        bl_base + p * 16 * ROWB + ko);
            }

            #pragma unroll
            for (int mt = 0; mt < 2; mt++)
                #pragma unroll
                for (int nt = 0; nt < 8; nt++) {
                    mma16816(d[mt][nt], Ah[mt], Bh[nt][0], Bh[nt][1]);
                    mma16816(d[mt][nt], Ah[mt], Bl[nt][0], Bl[nt][1]);
                    mma16816(d[mt][nt], Al[mt], Bh[nt][0], Bh[nt][1]);
                }
        }

        if (t + 1 < NSTEP) {
            sts_A(nb);
            CP_WAIT0();
        }
        __syncthreads();
    }

    // epilogue
    #pragma unroll
    for (int nt = 0; nt < 8; nt++) {
        const int col = n0 + wn * 64 + nt * 8 + tig * 2;
        const float bx = __ldg(&bias[col]);
        const float by = __ldg(&bias[col + 1]);
        #pragma unroll
        for (int mt = 0; mt < 2; mt++) {
            const size_t r0 = (size_t)(m0 + wm * 32 + mt * 16 + gid);
            float2 v0 = make_float2(d[mt][nt][0] + bx, d[mt][nt][1] + by);
            float2 v1 = make_float2(d[mt][nt][2] + bx, d[mt][nt][3] + by);
            *(float2*)&C[r0 * N + col]       = v0;
            *(float2*)&C[(r0 + 8) * N + col] = v1;
        }
    }
}

__global__ __launch_bounds__(256)
void gemm_qkv_mma(const float* __restrict__ x, const float* __restrict__ bias)
{
    gemm_mma_body(x, g_wa_hi, g_wa_lo, bias, g_qkv, 3 * DMODEL);
}
__global__ __launch_bounds__(256)
void gemm_proj_mma(const float* __restrict__ bias, float* __restrict__ out)
{
    gemm_mma_body(g_att, g_wp_hi, g_wp_lo, bias, out, DMODEL);
}

// ---------------------------------------------------------------------------
// Causal flash attention (fp32 SIMT) — unchanged.
// ---------------------------------------------------------------------------
#define AST 68
#define ATT_SMEM (4 * 64 * AST * sizeof(float))

__global__ __launch_bounds__(256)
void attn_kernel()
{
    extern __shared__ float sm[];
    float* Qs = sm;
    float* Ks = sm + 64 * AST;
    float* Ps = sm + 2 * 64 * AST;
    float* Vs = sm + 3 * 64 * AST;

    const int tid = threadIdx.x;
    const int tx  = tid & 15;
    const int ty  = tid >> 4;
    const int tx4 = tx * 4;
    const int ty4 = ty * 4;
    const int qtile = blockIdx.x;
    const int bh    = blockIdx.y;
    const int b = bh >> 4;
    const int h = bh & 15;
    const int q0 = qtile * 64;

    const float* qbase = g_qkv + (size_t)(b * SEQ + q0) * QKV_LD + h * HDIM;
    const float* kbase = g_qkv + (size_t)(b * SEQ) * QKV_LD + DMODEL + h * HDIM;
    const float* vbase = kbase + DMODEL;

    #pragma unroll
    for (int it = 0; it < 4; it++) {
        int idx = tid + it * 256;
        int r   = idx >> 4;
        int dv  = (idx & 15) << 2;
        float4 v = *(const float4*)(qbase + (size_t)r * QKV_LD + dv);
        Qs[(dv + 0) * AST + r] = v.x;
        Qs[(dv + 1) * AST + r] = v.y;
        Qs[(dv + 2) * AST + r] = v.z;
        Qs[(dv + 3) * AST + r] = v.w;
    }

    float o[4][4];
    #pragma unroll
    for (int i = 0; i < 4; i++)
        #pragma unroll
        for (int j = 0; j < 4; j++) o[i][j] = 0.0f;
    float mrun[4] = {-1e30f, -1e30f, -1e30f, -1e30f};
    float lrun[4] = {0.0f, 0.0f, 0.0f, 0.0f};

    for (int jt = 0; jt <= qtile; jt++) {
        __syncthreads();
        #pragma unroll
        for (int it = 0; it < 4; it++) {
            int idx = tid + it * 256;
            int r   = idx >> 4;
            int dv  = (idx & 15) << 2;
            size_t goff = (size_t)(jt * 64 + r) * QKV_LD + dv;
            float4 kv = *(const float4*)(kbase + goff);
            Ks[(dv + 0) * AST + r] = kv.x;
            Ks[(dv + 1) * AST + r] = kv.y;
            Ks[(dv + 2) * AST + r] = kv.z;
            Ks[(dv + 3) * AST + r] = kv.w;
            float4 vv = *(const float4*)(vbase + goff);
            *(float4*)&Vs[r * AST + dv] = vv;
        }
        __syncthreads();

        float s[4][4];
        #pragma unroll
        for (int i = 0; i < 4; i++)
            #pragma unroll
            for (int j = 0; j < 4; j++) s[i][j] = 0.0f;

        #pragma unroll 8
        for (int d = 0; d < 64; d++) {
            float4 a  = *(const float4*)&Qs[d * AST + ty4];
            float4 bq = *(const float4*)&Ks[d * AST + tx4];
            const float af[4] = {a.x, a.y, a.z, a.w};
            const float bf[4] = {bq.x, bq.y, bq.z, bq.w};
            #pragma unroll
            for (int i = 0; i < 4; i++)
                #pragma unroll
                for (int j = 0; j < 4; j++)
                    s[i][j] = fmaf(af[i], bf[j], s[i][j]);
        }

        if (jt == qtile) {
            #pragma unroll
            for (int i = 0; i < 4; i++)
                #pragma unroll
                for (int j = 0; j < 4; j++)
                    s[i][j] = (tx4 + j > ty4 + i) ? -1e9f : s[i][j] * 0.125f;
        } else {
            #pragma unroll
            for (int i = 0; i < 4; i++)
                #pragma unroll
                for (int j = 0; j < 4; j++)
                    s[i][j] *= 0.125f;
        }

        float mt[4];
        #pragma unroll
        for (int i = 0; i < 4; i++)
            mt[i] = fmaxf(fmaxf(s[i][0], s[i][1]), fmaxf(s[i][2], s[i][3]));
        #pragma unroll
        for (int off = 8; off >= 1; off >>= 1)
            #pragma unroll
            for (int i = 0; i < 4; i++)
                mt[i] = fmaxf(mt[i], __shfl_xor_sync(0xffffffffu, mt[i], off));

        float fac[4];
        #pragma unroll
        for (int i = 0; i < 4; i++) {
            float mn = fmaxf(mrun[i], mt[i]);
            fac[i] = __expf(mrun[i] - mn);
            mrun[i] = mn;
        }

        float lt[4];
        #pragma unroll
        for (int i = 0; i < 4; i++) {
            lt[i] = 0.0f;
            #pragma unroll
            for (int j = 0; j < 4; j++) {
                s[i][j] = __expf(s[i][j] - mrun[i]);
                lt[i] += s[i][j];
            }
        }
        #pragma unroll
        for (int off = 8; off >= 1; off >>= 1)
            #pragma unroll
            for (int i = 0; i < 4; i++)
                lt[i] += __shfl_xor_sync(0xffffffffu, lt[i], off);

        #pragma unroll
        for (int i = 0; i < 4; i++) {
            lrun[i] = lrun[i] * fac[i] + lt[i];
            #pragma unroll
            for (int j = 0; j < 4; j++) o[i][j] *= fac[i];
        }

        #pragma unroll
        for (int i = 0; i < 4; i++)
            #pragma unroll
            for (int j = 0; j < 4; j++)
                Ps[(tx4 + j) * AST + ty4 + i] = s[i][j];
        __syncthreads();

        #pragma unroll 8
        for (int k = 0; k < 64; k++) {
            float4 a = *(const float4*)&Ps[k * AST + ty4];
            float4 v = *(const float4*)&Vs[k * AST + tx4];
            const float af[4] = {a.x, a.y, a.z, a.w};
            const float vf[4] = {v.x, v.y, v.z, v.w};
            #pragma unroll
            for (int i = 0; i < 4; i++)
                #pragma unroll
                for (int j = 0; j < 4; j++)
                    o[i][j] = fmaf(af[i], vf[j], o[i][j]);
        }
    }

    #pragma unroll
    for (int i = 0; i < 4; i++) {
        float inv = 1.0f / lrun[i];
        size_t row = (size_t)(b * SEQ + q0 + ty4 + i);
        float4 c = make_float4(o[i][0] * inv, o[i][1] * inv,
                               o[i][2] * inv, o[i][3] * inv);
        *(float4*)&g_att[row * DMODEL + h * HDIM + tx4] = c;
    }
}

// ---------------------------------------------------------------------------
extern "C" void kernel_launch(void* const* d_in, const int* in_sizes, int n_in,
                              void* d_out, int out_size)
{
    const float* x      = (const float*)d_in[0];
    const float* w_attn = (const float*)d_in[1];
    const float* b_attn = (const float*)d_in[2];
    const float* w_proj = (const float*)d_in[3];
    const float* b_proj = (const float*)d_in[4];
    float* out = (float*)d_out;

    cudaFuncSetAttribute(attn_kernel,
                         cudaFuncAttributeMaxDynamicSharedMemorySize, (int)ATT_SMEM);
    cudaFuncSetAttribute(gemm_qkv_mma,
                         cudaFuncAttributeMaxDynamicSharedMemorySize, GSMEM);
    cudaFuncSetAttribute(gemm_proj_mma,
                         cudaFuncAttributeMaxDynamicSharedMemorySize, GSMEM);

    trans_wa<<<dim3(3 * DMODEL / 32, DMODEL / 32), dim3(32, 8)>>>(w_attn);
    trans_wp<<<dim3(DMODEL / 32, DMODEL / 32), dim3(32, 8)>>>(w_proj);

    gemm_qkv_mma<<<dim3(3 * DMODEL / 128, MTOT / 128), 256, GSMEM>>>(x, b_attn);
    attn_kernel<<<dim3(SEQ / 64, BATCH * NHEAD), 256, ATT_SMEM>>>();
    gemm_proj_mma<<<dim3(DMODEL / 128, MTOT / 128), 256, GSMEM>>>(b_proj, out);
}

// round 4
// speedup vs baseline: 2.6407x; 1.8007x over previous
#include <cuda_runtime.h>
#include <cuda_bf16.h>
#include <cstdint>

// ---------------------------------------------------------------------------
// GPT-2 attention block, all-tensor-core (mma.sync bf16 hi/lo fp32 emulation).
//   qkv  = x @ w_attn + b_attn  -> mma GEMM, epilogue emits q/k/v bf16 hi/lo
//   att  = causal flash attention, fully mma.sync (3-pass hi/lo both GEMMs)
//   out  = att @ w_proj + b_proj -> mma GEMM
// ---------------------------------------------------------------------------

#define BATCH  4
#define SEQ    2048
#define DMODEL 1024
#define NHEAD  16
#define HDIM   64
#define MTOT   (BATCH * SEQ)
#define GK     1024

// Scratch (allocation-free rule: __device__ globals)
__device__ float g_att[(size_t)MTOT * DMODEL];                 // 32 MB
__device__ __nv_bfloat16 g_wa_hi[3 * DMODEL * DMODEL];
__device__ __nv_bfloat16 g_wa_lo[3 * DMODEL * DMODEL];
__device__ __nv_bfloat16 g_wp_hi[DMODEL * DMODEL];
__device__ __nv_bfloat16 g_wp_lo[DMODEL * DMODEL];
// q/k/v, head-separated [bh][s][64], bf16 hi/lo (q pre-scaled by 1/8)
#define QKV_ELEMS ((size_t)NHEAD * BATCH * SEQ * HDIM)
__device__ __nv_bfloat16 g_q_hi[QKV_ELEMS];
__device__ __nv_bfloat16 g_q_lo[QKV_ELEMS];
__device__ __nv_bfloat16 g_k_hi[QKV_ELEMS];
__device__ __nv_bfloat16 g_k_lo[QKV_ELEMS];
__device__ __nv_bfloat16 g_v_hi[QKV_ELEMS];
__device__ __nv_bfloat16 g_v_lo[QKV_ELEMS];

// ---------------------------------------------------------------------------
__device__ __forceinline__ uint32_t smem_to_u32(const void* p) {
    uint32_t a;
    asm("{ .reg .u64 t; cvta.to.shared.u64 t, %1; cvt.u32.u64 %0, t; }"
        : "=r"(a) : "l"(p));
    return a;
}
__device__ __forceinline__ void ldsm_x4(uint32_t& r0, uint32_t& r1,
                                        uint32_t& r2, uint32_t& r3, uint32_t a) {
    asm volatile("ldmatrix.sync.aligned.m8n8.x4.shared.b16 {%0,%1,%2,%3}, [%4];"
                 : "=r"(r0), "=r"(r1), "=r"(r2), "=r"(r3) : "r"(a));
}
__device__ __forceinline__ void ldsm_x4_t(uint32_t& r0, uint32_t& r1,
                                          uint32_t& r2, uint32_t& r3, uint32_t a) {
    asm volatile("ldmatrix.sync.aligned.m8n8.x4.trans.shared.b16 {%0,%1,%2,%3}, [%4];"
                 : "=r"(r0), "=r"(r1), "=r"(r2), "=r"(r3) : "r"(a));
}
__device__ __forceinline__ void mma16816(float* d, const uint32_t* a,
                                         uint32_t b0, uint32_t b1) {
    asm volatile(
        "mma.sync.aligned.m16n8k16.row.col.f32.bf16.bf16.f32 "
        "{%0,%1,%2,%3}, {%4,%5,%6,%7}, {%8,%9}, {%0,%1,%2,%3};"
        : "+f"(d[0]), "+f"(d[1]), "+f"(d[2]), "+f"(d[3])
        : "r"(a[0]), "r"(a[1]), "r"(a[2]), "r"(a[3]), "r"(b0), "r"(b1));
}
#define CP_ASYNC8(dst, src) \
    asm volatile("cp.async.ca.shared.global [%0], [%1], 8;" :: "r"(dst), "l"(src) : "memory")
#define CP_ASYNC16(dst, src) \
    asm volatile("cp.async.cg.shared.global [%0], [%1], 16;" :: "r"(dst), "l"(src) : "memory")
#define CP_COMMIT() asm volatile("cp.async.commit_group;" ::: "memory")
#define CP_WAIT0()  asm volatile("cp.async.wait_group 0;" ::: "memory")

// split x,y into bf16 hi pack and lo pack
__device__ __forceinline__ void hilo2(float x, float y, uint32_t& hi, uint32_t& lo) {
    __nv_bfloat162 h = __floats2bfloat162_rn(x, y);
    hi = *(uint32_t*)&h;
    float hx = __bfloat162float(h.x), hy = __bfloat162float(h.y);
    __nv_bfloat162 l = __floats2bfloat162_rn(x - hx, y - hy);
    lo = *(uint32_t*)&l;
}

// ---------------------------------------------------------------------------
// Weight transpose + bf16 hi/lo split:  w[K][N] fp32 -> out[N][K] bf16 x2
// ---------------------------------------------------------------------------
__device__ __forceinline__ void transpose_split_body(
    const float* __restrict__ w, __nv_bfloat16* __restrict__ hi,
    __nv_bfloat16* __restrict__ lo, int K, int N)
{
    __shared__ float t[32][33];
    const int n0 = blockIdx.x * 32, k0 = blockIdx.y * 32;
    const int tx = threadIdx.x, ty = threadIdx.y;
    #pragma unroll
    for (int i = ty; i < 32; i += 8)
        t[i][tx] = w[(size_t)(k0 + i) * N + n0 + tx];
    __syncthreads();
    #pragma unroll
    for (int i = ty; i < 32; i += 8) {
        float v = t[tx][i];
        __nv_bfloat16 h = __float2bfloat16(v);
        size_t idx = (size_t)(n0 + i) * K + k0 + tx;
        hi[idx] = h;
        lo[idx] = __float2bfloat16(v - __bfloat162float(h));
    }
}
__global__ void trans_wa(const float* __restrict__ w) {
    transpose_split_body(w, g_wa_hi, g_wa_lo, DMODEL, 3 * DMODEL);
}
__global__ void trans_wp(const float* __restrict__ w) {
    transpose_split_body(w, g_wp_hi, g_wp_lo, DMODEL, DMODEL);
}

// ---------------------------------------------------------------------------
// mma.sync GEMM: CTA 128x128, K-step 32, 8 warps (4x2), warp tile 32x64.
// MODE 0: C = A*BT + bias (fp32 out).  MODE 1: qkv split epilogue.
// ---------------------------------------------------------------------------
#define TK      32
#define NSTEP   (GK / TK)
#define ROWB    80
#define TILEB   (128 * ROWB)
#define SM_A(s, h) (((s) * 2 + (h)) * TILEB)
#define SM_B(s, h) (40960 + ((s) * 2 + (h)) * TILEB)
#define GSMEM   81920

template <int MODE>
__device__ __forceinline__ void gemm_mma_body(
    const float* __restrict__ A, const __nv_bfloat16* __restrict__ BTh,
    const __nv_bfloat16* __restrict__ BTl, const float* __restrict__ bias,
    float* __restrict__ C, int N)
{
    extern __shared__ char smem[];
    const uint32_t sb = smem_to_u32(smem);
    const int tid  = threadIdx.x;
    const int wid  = tid >> 5;
    const int lane = tid & 31;
    const int wm   = wid & 3;
    const int wn   = wid >> 2;
    const int gid  = lane >> 2;
    const int tig  = lane & 3;
    const int m0   = blockIdx.y * 128;
    const int n0   = blockIdx.x * 128;

    float d[2][8][4];
    #pragma unroll
    for (int mt = 0; mt < 2; mt++)
        #pragma unroll
        for (int nt = 0; nt < 8; nt++)
            #pragma unroll
            for (int c = 0; c < 4; c++) d[mt][nt][c] = 0.0f;

    const uint32_t a_off = (uint32_t)((wm * 32 + (lane & 7) + ((lane >> 3) & 1) * 8) * ROWB
                                      + (lane >> 4) * 16);
    const uint32_t b_off = (uint32_t)((wn * 64 + ((lane >> 4) & 1) * 8 + (lane & 7)) * ROWB
                                      + ((lane >> 3) & 1) * 16);

    float4 areg[4];
    auto ldg_A = [&](int t) {
        const int k0 = t * TK;
        #pragma unroll
        for (int i = 0; i < 4; i++) {
            int idx = tid + i * 256;
            int row = idx >> 3;
            int c4  = idx & 7;
            areg[i] = *(const float4*)(A + (size_t)(m0 + row) * GK + k0 + c4 * 4);
        }
    };
    auto cpasync_B = [&](int t, int s) {
        const int k0 = t * TK;
        #pragma unroll
        for (int i = 0; i < 8; i++) {
            int idx  = tid + i * 256;
            int half = idx >> 10;
            int row  = (idx >> 3) & 127;
            int c    = idx & 7;
            uint32_t dst = sb + SM_B(s, half) + row * ROWB + c * 8;
            const __nv_bfloat16* src =
                (half ? BTl : BTh) + (size_t)(n0 + row) * GK + k0 + c * 4;
            CP_ASYNC8(dst, src);
        }
        CP_COMMIT();
    };
    auto sts_A = [&](int s) {
        #pragma unroll
        for (int i = 0; i < 4; i++) {
            int idx = tid + i * 256;
            int row = idx >> 3;
            int c4  = idx & 7;
            float4 v = areg[i];
            float hx = __bfloat162float(__float2bfloat16(v.x));
            float hy = __bfloat162float(__float2bfloat16(v.y));
            float hz = __bfloat162float(__float2bfloat16(v.z));
            float hw = __bfloat162float(__float2bfloat16(v.w));
            __nv_bfloat162 h0 = __floats2bfloat162_rn(hx, hy);
            __nv_bfloat162 h1 = __floats2bfloat162_rn(hz, hw);
            __nv_bfloat162 l0 = __floats2bfloat162_rn(v.x - hx, v.y - hy);
            __nv_bfloat162 l1 = __floats2bfloat162_rn(v.z - hz, v.w - hw);
            uint32_t off = (uint32_t)(row * ROWB + c4 * 8);
            *(__nv_bfloat162*)(smem + SM_A(s, 0) + off)     = h0;
            *(__nv_bfloat162*)(smem + SM_A(s, 0) + off + 4) = h1;
            *(__nv_bfloat162*)(smem + SM_A(s, 1) + off)     = l0;
            *(__nv_bfloat162*)(smem + SM_A(s, 1) + off + 4) = l1;
        }
    };

    ldg_A(0);
    cpasync_B(0, 0);
    sts_A(0);
    CP_WAIT0();
    __syncthreads();

    #pragma unroll 1
    for (int t = 0; t < NSTEP; t++) {
        const int b  = t & 1;
        const int nb = b ^ 1;
        if (t + 1 < NSTEP) {
            ldg_A(t + 1);
            cpasync_B(t + 1, nb);
        }
        const uint32_t ah_base = sb + SM_A(b, 0) + a_off;
        const uint32_t al_base = sb + SM_A(b, 1) + a_off;
        const uint32_t bh_base = sb + SM_B(b, 0) + b_off;
        const uint32_t bl_base = sb + SM_B(b, 1) + b_off;

        #pragma unroll
        for (int kk = 0; kk < 2; kk++) {
            const uint32_t ko = kk * 32;
            uint32_t Ah[2][4], Al[2][4];
            ldsm_x4(Ah[0][0], Ah[0][1], Ah[0][2], Ah[0][3], ah_base + ko);
            ldsm_x4(Ah[1][0], Ah[1][1], Ah[1][2], Ah[1][3], ah_base + 16 * ROWB + ko);
            ldsm_x4(Al[0][0], Al[0][1], Al[0][2], Al[0][3], al_base + ko);
            ldsm_x4(Al[1][0], Al[1][1], Al[1][2], Al[1][3], al_base + 16 * ROWB + ko);

            uint32_t Bh[8][2], Bl[8][2];
            #pragma unroll
            for (int p = 0; p < 4; p++) {
                ldsm_x4(Bh[2 * p][0], Bh[2 * p][1], Bh[2 * p + 1][0], Bh[2 * p + 1][1],
                        bh_base + p * 16 * ROWB + ko);
                ldsm_x4(Bl[2 * p][0], Bl[2 * p][1], Bl[2 * p + 1][0], Bl[2 * p + 1][1],
                        bl_base + p * 16 * ROWB + ko);
            }
            #pragma unroll
            for (int mt = 0; mt < 2; mt++)
                #pragma unroll
                for (int nt = 0; nt < 8; nt++) {
                    mma16816(d[mt][nt], Ah[mt], Bh[nt][0], Bh[nt][1]);
                    mma16816(d[mt][nt], Ah[mt], Bl[nt][0], Bl[nt][1]);
                    mma16816(d[mt][nt], Al[mt], Bh[nt][0], Bh[nt][1]);
                }
        }
        if (t + 1 < NSTEP) {
            sts_A(nb);
            CP_WAIT0();
        }
        __syncthreads();
    }

    if (MODE == 0) {
        #pragma unroll
        for (int nt = 0; nt < 8; nt++) {
            const int col = n0 + wn * 64 + nt * 8 + tig * 2;
            const float bx = __ldg(&bias[col]);
            const float by = __ldg(&bias[col + 1]);
            #pragma unroll
            for (int mt = 0; mt < 2; mt++) {
                const size_t r0 = (size_t)(m0 + wm * 32 + mt * 16 + gid);
                *(float2*)&C[r0 * N + col] =
                    make_float2(d[mt][nt][0] + bx, d[mt][nt][1] + by);
                *(float2*)&C[(r0 + 8) * N + col] =
                    make_float2(d[mt][nt][2] + bx, d[mt][nt][3] + by);
            }
        }
    } else {
        // qkv split epilogue: bf16 hi/lo, head-separated layout, q scaled 1/8
        #pragma unroll
        for (int nt = 0; nt < 8; nt++) {
            const int col = n0 + wn * 64 + nt * 8 + tig * 2;
            const float bx = __ldg(&bias[col]);
            const float by = __ldg(&bias[col + 1]);
            const int sel = col >> 10;
            const float sc = (sel == 0) ? 0.125f : 1.0f;
            __nv_bfloat16* dh = (sel == 0) ? g_q_hi : (sel == 1) ? g_k_hi : g_v_hi;
            __nv_bfloat16* dl = (sel == 0) ? g_q_lo : (sel == 1) ? g_k_lo : g_v_lo;
            const int hh = (col >> 6) & 15;
            const int dd = col & 63;
            #pragma unroll
            for (int mt = 0; mt < 2; mt++) {
                const int row = m0 + wm * 32 + mt * 16 + gid;
                const int bb = row >> 11, ss = row & 2047;
                const size_t base = ((size_t)(bb * NHEAD + hh) * SEQ + ss) * HDIM + dd;
                float v0 = (d[mt][nt][0] + bx) * sc, v1 = (d[mt][nt][1] + by) * sc;
                float v2 = (d[mt][nt][2] + bx) * sc, v3 = (d[mt][nt][3] + by) * sc;
                uint32_t h01, l01, h23, l23;
                hilo2(v0, v1, h01, l01);
                hilo2(v2, v3, h23, l23);
                *(uint32_t*)&dh[base]            = h01;
                *(uint32_t*)&dl[base]            = l01;
                *(uint32_t*)&dh[base + 8 * HDIM] = h23;
                *(uint32_t*)&dl[base + 8 * HDIM] = l23;
            }
        }
    }
}

__global__ __launch_bounds__(256)
void gemm_qkv_mma(const float* __restrict__ x, const float* __restrict__ bias)
{
    gemm_mma_body<1>(x, g_wa_hi, g_wa_lo, bias, nullptr, 3 * DMODEL);
}
__global__ __launch_bounds__(256)
void gemm_proj_mma(const float* __restrict__ bias, float* __restrict__ out)
{
    gemm_mma_body<0>(g_att, g_wp_hi, g_wp_lo, bias, out, DMODEL);
}

// ---------------------------------------------------------------------------
// Causal flash attention, mma.sync bf16 hi/lo (3-pass both GEMMs).
// CTA = (128 q rows, bh). 8 warps x m16. KV tile 64, double buffered.
// ---------------------------------------------------------------------------
#define ASTR   144                       // smem row stride bytes (64 bf16 + pad)
#define SQ_H   0
#define SQ_L   (128 * ASTR)              // 18432
#define AKV0   (2 * 128 * ASTR)          // 36864
#define KVBUF  (4 * 64 * ASTR)           // 36864 (Khi,Klo,Vhi,Vlo)
#define SKV(s, t) (AKV0 + (s) * KVBUF + (t) * (64 * ASTR))
#define ATT_SMEM (AKV0 + 2 * KVBUF)      // 110592

__global__ __launch_bounds__(256, 1)
void attn_mma()
{
    extern __shared__ char smem[];
    const uint32_t sb = smem_to_u32(smem);
    const int tid  = threadIdx.x;
    const int wid  = tid >> 5;
    const int lane = tid & 31;
    const int g    = lane >> 2;
    const int t2   = (lane & 3) * 2;
    const int qi   = (int)(gridDim.x - 1 - blockIdx.x);  // heavy tiles first
    const int bh   = blockIdx.y;
    const int bb   = bh >> 4;
    const int h    = bh & 15;
    const int q0   = qi * 128;
    const int wm0  = wid * 16;

    const size_t head_base = (size_t)bh * SEQ * HDIM;

    auto load_kv = [&](int jt, int s) {
        #pragma unroll
        for (int tp = 0; tp < 4; tp++) {
            const __nv_bfloat16* bp =
                (tp == 0) ? g_k_hi : (tp == 1) ? g_k_lo : (tp == 2) ? g_v_hi : g_v_lo;
            #pragma unroll
            for (int j = 0; j < 2; j++) {
                int idx = tid + (tp * 2 + j) * 256;
                int row = (idx >> 3) & 63;
                int c   = idx & 7;
                uint32_t dst = sb + SKV(s, tp) + row * ASTR + c * 16;
                const __nv_bfloat16* src =
                    bp + head_base + (size_t)(jt * 64 + row) * HDIM + c * 8;
                CP_ASYNC16(dst, src);
            }
        }
        CP_COMMIT();
    };

    load_kv(0, 0);

    // Q tile (hi/lo) -> smem
    {
        const __nv_bfloat16* qh_g = g_q_hi + head_base + (size_t)q0 * HDIM;
        const __nv_bfloat16* ql_g = g_q_lo + head_base + (size_t)q0 * HDIM;
        #pragma unroll
        for (int i = 0; i < 4; i++) {
            int idx = tid + i * 256;
            int row = idx >> 3;
            int c   = idx & 7;
            *(uint4*)(smem + SQ_H + row * ASTR + c * 16) =
                *(const uint4*)(qh_g + (size_t)row * HDIM + c * 8);
            *(uint4*)(smem + SQ_L + row * ASTR + c * 16) =
                *(const uint4*)(ql_g + (size_t)row * HDIM + c * 8);
        }
    }
    CP_WAIT0();
    __syncthreads();

    // Q fragments (A, m16k16 x 4 k-tiles)
    uint32_t qh[4][4], ql[4][4];
    {
        uint32_t qaddr = sb + SQ_H +
            (uint32_t)((wm0 + (lane & 7) + ((lane >> 3) & 1) * 8) * ASTR + (lane >> 4) * 16);
        #pragma unroll
        for (int kt = 0; kt < 4; kt++) {
            ldsm_x4(qh[kt][0], qh[kt][1], qh[kt][2], qh[kt][3], qaddr + kt * 32);
            ldsm_x4(ql[kt][0], ql[kt][1], ql[kt][2], ql[kt][3],
                    qaddr + (SQ_L - SQ_H) + kt * 32);
        }
    }

    float o[8][4];
    #pragma unroll
    for (int nt = 0; nt < 8; nt++)
        #pragma unroll
        for (int c = 0; c < 4; c++) o[nt][c] = 0.0f;
    float mrun0 = -1e30f, mrun1 = -1e30f, lrun0 = 0.0f, lrun1 = 0.0f;

    const int njt = 2 * qi + 2;
    const uint32_t k_off =
        (uint32_t)(((lane & 7) + ((lane >> 4) & 1) * 8) * ASTR + ((lane >> 3) & 1) * 16);
    const uint32_t v_off =
        (uint32_t)(((lane & 7) + ((lane >> 3) & 1) * 8) * ASTR + (lane >> 4) * 16);

    #pragma unroll 1
    for (int jt = 0; jt < njt; jt++) {
        const int bfr = jt & 1;
        if (jt + 1 < njt) load_kv(jt + 1, bfr ^ 1);

        // ---- S = (Qh+Ql)(Kh+Kl)^T  (3 passes)
        float s[8][4];
        #pragma unroll
        for (int nt = 0; nt < 8; nt++)
            #pragma unroll
            for (int c = 0; c < 4; c++) s[nt][c] = 0.0f;

        const uint32_t kaddr = sb + SKV(bfr, 0) + k_off;
        #pragma unroll
        for (int kt = 0; kt < 4; kt++) {
            #pragma unroll
            for (int np = 0; np < 4; np++) {
                uint32_t a0, a1, a2, a3, b0, b1, b2, b3;
                uint32_t base = kaddr + np * (16 * ASTR) + kt * 32;
                ldsm_x4(a0, a1, a2, a3, base);                 // K hi
                ldsm_x4(b0, b1, b2, b3, base + 64 * ASTR);     // K lo
                mma16816(s[2 * np],     qh[kt], a0, a1);
                mma16816(s[2 * np + 1], qh[kt], a2, a3);
                mma16816(s[2 * np],     ql[kt], a0, a1);
                mma16816(s[2 * np + 1], ql[kt], a2, a3);
                mma16816(s[2 * np],     qh[kt], b0, b1);
                mma16816(s[2 * np + 1], qh[kt], b2, b3);
            }
        }

        // ---- causal mask (warp-uniform branch)
        if (jt * 64 + 63 > q0 + wm0) {
            const int row0 = q0 + wm0 + g;
            #pragma unroll
            for (int nt = 0; nt < 8; nt++) {
                const int col = jt * 64 + nt * 8 + t2;
                #pragma unroll
                for (int c = 0; c < 4; c++) {
                    int cc = col + (c & 1);
                    int rr = row0 + (c >> 1) * 8;
                    if (cc > rr) s[nt][c] = -1e30f;
                }
            }
        }

        // ---- online softmax (rows g, g+8)
        float mt0 = -1e30f, mt1 = -1e30f;
        #pragma unroll
        for (int nt = 0; nt < 8; nt++) {
            mt0 = fmaxf(mt0, fmaxf(s[nt][0], s[nt][1]));
            mt1 = fmaxf(mt1, fmaxf(s[nt][2], s[nt][3]));
        }
        mt0 = fmaxf(mt0, __shfl_xor_sync(0xffffffffu, mt0, 1));
        mt0 = fmaxf(mt0, __shfl_xor_sync(0xffffffffu, mt0, 2));
        mt1 = fmaxf(mt1, __shfl_xor_sync(0xffffffffu, mt1, 1));
        mt1 = fmaxf(mt1, __shfl_xor_sync(0xffffffffu, mt1, 2));

        const float mn0 = fmaxf(mrun0, mt0);
        const float mn1 = fmaxf(mrun1, mt1);
        const float f0 = __expf(mrun0 - mn0);
        const float f1 = __expf(mrun1 - mn1);
        mrun0 = mn0; mrun1 = mn1;

        float lt0 = 0.0f, lt1 = 0.0f;
        #pragma unroll
        for (int nt = 0; nt < 8; nt++) {
            s[nt][0] = __expf(s[nt][0] - mn0); lt0 += s[nt][0];
            s[nt][1] = __expf(s[nt][1] - mn0); lt0 += s[nt][1];
            s[nt][2] = __expf(s[nt][2] - mn1); lt1 += s[nt][2];
            s[nt][3] = __expf(s[nt][3] - mn1); lt1 += s[nt][3];
        }
        lt0 += __shfl_xor_sync(0xffffffffu, lt0, 1);
        lt0 += __shfl_xor_sync(0xffffffffu, lt0, 2);
        lt1 += __shfl_xor_sync(0xffffffffu, lt1, 1);
        lt1 += __shfl_xor_sync(0xffffffffu, lt1, 2);
        lrun0 = lrun0 * f0 + lt0;
        lrun1 = lrun1 * f1 + lt1;
        #pragma unroll
        for (int nt = 0; nt < 8; nt++) {
            o[nt][0] *= f0; o[nt][1] *= f0;
            o[nt][2] *= f1; o[nt][3] *= f1;
        }

        // ---- P fragments from S accumulators (C->A identity), hi/lo
        uint32_t aph[4][4], apl[4][4];
        #pragma unroll
        for (int kt = 0; kt < 4; kt++) {
            hilo2(s[2 * kt][0],     s[2 * kt][1],     aph[kt][0], apl[kt][0]);
            hilo2(s[2 * kt][2],     s[2 * kt][3],     aph[kt][1], apl[kt][1]);
            hilo2(s[2 * kt + 1][0], s[2 * kt + 1][1], aph[kt][2], apl[kt][2]);
            hilo2(s[2 * kt + 1][2], s[2 * kt + 1][3], aph[kt][3], apl[kt][3]);
        }

        // ---- O += P @ V  (3 passes), V via ldmatrix.trans
        const uint32_t vaddr = sb + SKV(bfr, 2) + v_off;
        #pragma unroll
        for (int kt = 0; kt < 4; kt++) {
            #pragma unroll
            for (int np = 0; np < 4; np++) {
                uint32_t v0, v1, v2, v3, w0, w1, w2, w3;
                uint32_t base = vaddr + kt * (16 * ASTR) + np * 32;
                ldsm_x4_t(v0, v1, v2, v3, base);               // V hi
                ldsm_x4_t(w0, w1, w2, w3, base + 64 * ASTR);   // V lo
                mma16816(o[2 * np],     aph[kt], v0, v1);
                mma16816(o[2 * np + 1], aph[kt], v2, v3);
                mma16816(o[2 * np],     apl[kt], v0, v1);
                mma16816(o[2 * np + 1], apl[kt], v2, v3);
                mma16816(o[2 * np],     aph[kt], w0, w1);
                mma16816(o[2 * np + 1], aph[kt], w2, w3);
            }
        }

        CP_WAIT0();
        __syncthreads();
    }

    // ---- normalize + write merged-head [token][D] fp32
    const float inv0 = 1.0f / lrun0;
    const float inv1 = 1.0f / lrun1;
    const size_t r0 = (size_t)bb * SEQ + q0 + wm0 + g;
    const int colb = h * HDIM + t2;
    #pragma unroll
    for (int nt = 0; nt < 8; nt++) {
        *(float2*)&g_att[r0 * DMODEL + colb + nt * 8] =
            make_float2(o[nt][0] * inv0, o[nt][1] * inv0);
        *(float2*)&g_att[(r0 + 8) * DMODEL + colb + nt * 8] =
            make_float2(o[nt][2] * inv1, o[nt][3] * inv1);
    }
}

// ---------------------------------------------------------------------------
extern "C" void kernel_launch(void* const* d_in, const int* in_sizes, int n_in,
                              void* d_out, int out_size)
{
    const float* x      = (const float*)d_in[0];
    const float* w_attn = (const float*)d_in[1];
    const float* b_attn = (const float*)d_in[2];
    const float* w_proj = (const float*)d_in[3];
    const float* b_proj = (const float*)d_in[4];
    float* out = (float*)d_out;

    cudaFuncSetAttribute(attn_mma,
                         cudaFuncAttributeMaxDynamicSharedMemorySize, ATT_SMEM);
    cudaFuncSetAttribute(gemm_qkv_mma,
                         cudaFuncAttributeMaxDynamicSharedMemorySize, GSMEM);
    cudaFuncSetAttribute(gemm_proj_mma,
                         cudaFuncAttributeMaxDynamicSharedMemorySize, GSMEM);

    trans_wa<<<dim3(3 * DMODEL / 32, DMODEL / 32), dim3(32, 8)>>>(w_attn);
    trans_wp<<<dim3(DMODEL / 32, DMODEL / 32), dim3(32, 8)>>>(w_proj);

    gemm_qkv_mma<<<dim3(3 * DMODEL / 128, MTOT / 128), 256, GSMEM>>>(x, b_attn);
    attn_mma<<<dim3(SEQ / 128, BATCH * NHEAD), 256, ATT_SMEM>>>();
    gemm_proj_mma<<<dim3(DMODEL / 128, MTOT / 128), 256, GSMEM>>>(b_proj, out);
}